// round 1
// baseline (speedup 1.0000x reference)
#include <cuda_runtime.h>
#include <cstddef>

#define HW     2304      // 48*48 tokens
#define CH     768       // embed dim
#define NH     12        // heads
#define HD     64        // head dim
#define SH     48        // spatial side
#define QSCALE 0.125f    // 64^-0.5
#define OUT_ELEMS (HW * CH)   // 1769472 — offset of attn region in d_out

// -------- scratch (no allocations allowed) --------
__device__ float g_Q[HW * CH];
__device__ float g_K[HW * CH];
__device__ float g_V[HW * CH];
__device__ float g_OH[HW * CH];
__device__ float g_relh[NH * HW * SH];
__device__ float g_relw[NH * HW * SH];

// ============================================================
// GEMM-NT + bias:  C[m,n] = sum_k A[m,k] * W[n,k] + bias[n]
// M=2304, N=768, K=768.  BM=128, BN=64, BK=32, 256 threads, 8x4/thread.
// asel: -1 -> A = Aext (hidden_states), 0 -> A = g_OH
// csel: 0/1/2 -> g_Q/g_K/g_V, 3 -> Cext
// ============================================================
__global__ __launch_bounds__(256) void gemm_nt_bias(
    const float* __restrict__ Aext, int asel,
    const float* __restrict__ W,
    const float* __restrict__ bias,
    float* __restrict__ Cext, int csel)
{
    const float* A = (asel < 0) ? Aext : g_OH;
    float* Cp = (csel == 0) ? g_Q : (csel == 1) ? g_K : (csel == 2) ? g_V : Cext;

    __shared__ float As[32][129];   // [k][m], pad 129 -> conflict-free transposed stores
    __shared__ float Bs[32][65];    // [k][n]

    const int bm = blockIdx.x * 128;
    const int bn = blockIdx.y * 64;
    const int tid = threadIdx.x;
    const int tx = tid & 15;        // n: 4 each
    const int ty = tid >> 4;        // m: 8 each

    float acc[8][4];
    #pragma unroll
    for (int i = 0; i < 8; i++)
        #pragma unroll
        for (int j = 0; j < 4; j++) acc[i][j] = 0.f;

    for (int k0 = 0; k0 < CH; k0 += 32) {
        // A tile: 128 x 32 = 1024 float4 loads across 256 threads (4 each)
        #pragma unroll
        for (int i = 0; i < 4; i++) {
            int idx = tid + i * 256;
            int r = idx >> 3, c4 = idx & 7;
            float4 v = *reinterpret_cast<const float4*>(
                &A[(size_t)(bm + r) * CH + k0 + c4 * 4]);
            As[c4 * 4 + 0][r] = v.x; As[c4 * 4 + 1][r] = v.y;
            As[c4 * 4 + 2][r] = v.z; As[c4 * 4 + 3][r] = v.w;
        }
        // B tile: 64 x 32 = 512 float4 (2 each)
        #pragma unroll
        for (int i = 0; i < 2; i++) {
            int idx = tid + i * 256;
            int r = idx >> 3, c4 = idx & 7;
            float4 v = *reinterpret_cast<const float4*>(
                &W[(size_t)(bn + r) * CH + k0 + c4 * 4]);
            Bs[c4 * 4 + 0][r] = v.x; Bs[c4 * 4 + 1][r] = v.y;
            Bs[c4 * 4 + 2][r] = v.z; Bs[c4 * 4 + 3][r] = v.w;
        }
        __syncthreads();
        #pragma unroll
        for (int k = 0; k < 32; k++) {
            float a[8], b[4];
            #pragma unroll
            for (int i = 0; i < 8; i++) a[i] = As[k][ty * 8 + i];
            #pragma unroll
            for (int j = 0; j < 4; j++) b[j] = Bs[k][tx * 4 + j];
            #pragma unroll
            for (int i = 0; i < 8; i++)
                #pragma unroll
                for (int j = 0; j < 4; j++) acc[i][j] += a[i] * b[j];
        }
        __syncthreads();
    }

    #pragma unroll
    for (int i = 0; i < 8; i++) {
        int m = bm + ty * 8 + i;
        #pragma unroll
        for (int j = 0; j < 4; j++) {
            int n = bn + tx * 4 + j;
            Cp[(size_t)m * CH + n] = acc[i][j] + bias[n];
        }
    }
}

// ============================================================
// rel-pos bias rows: relh[h,m,k] = q[h,m,:] . rel_pos_h[y-k+47,:]
//                     relw[h,m,k] = q[h,m,:] . rel_pos_w[x-k+47,:]
// grid (2304, 12), 96 threads
// ============================================================
__global__ __launch_bounds__(96) void relpos_kernel(
    const float* __restrict__ rph, const float* __restrict__ rpw)
{
    int m = blockIdx.x;
    int h = blockIdx.y;
    int y = m / SH, x = m % SH;
    __shared__ float q[HD];
    int t = threadIdx.x;
    if (t < HD) q[t] = g_Q[(size_t)m * CH + h * HD + t];
    __syncthreads();

    if (t < SH) {
        const float* r = &rph[(size_t)(y - t + SH - 1) * HD];
        float s = 0.f;
        #pragma unroll
        for (int d = 0; d < HD; d++) s += q[d] * r[d];
        g_relh[((size_t)h * HW + m) * SH + t] = s;
    } else {
        int k = t - SH;
        const float* r = &rpw[(size_t)(x - k + SH - 1) * HD];
        float s = 0.f;
        #pragma unroll
        for (int d = 0; d < HD; d++) s += q[d] * r[d];
        g_relw[((size_t)h * HW + m) * SH + k] = s;
    }
}

// ============================================================
// scores: attn[h,m,n] = SCALE * (q_h[m] . k_h[n]) + relh[h,m,n/48] + relw[h,m,n%48]
// per head GEMM-NT: M=N=2304, K=64. grid (18, 36, 12)
// ============================================================
__global__ __launch_bounds__(256) void scores_kernel(float* __restrict__ attn)
{
    const int h = blockIdx.z;
    const int bm = blockIdx.x * 128;
    const int bn = blockIdx.y * 64;

    __shared__ float As[32][129];
    __shared__ float Bs[32][65];

    const int tid = threadIdx.x;
    const int tx = tid & 15;
    const int ty = tid >> 4;

    float acc[8][4];
    #pragma unroll
    for (int i = 0; i < 8; i++)
        #pragma unroll
        for (int j = 0; j < 4; j++) acc[i][j] = 0.f;

    for (int k0 = 0; k0 < HD; k0 += 32) {
        #pragma unroll
        for (int i = 0; i < 4; i++) {
            int idx = tid + i * 256;
            int r = idx >> 3, c4 = idx & 7;
            float4 v = *reinterpret_cast<const float4*>(
                &g_Q[(size_t)(bm + r) * CH + h * HD + k0 + c4 * 4]);
            As[c4 * 4 + 0][r] = v.x; As[c4 * 4 + 1][r] = v.y;
            As[c4 * 4 + 2][r] = v.z; As[c4 * 4 + 3][r] = v.w;
        }
        #pragma unroll
        for (int i = 0; i < 2; i++) {
            int idx = tid + i * 256;
            int r = idx >> 3, c4 = idx & 7;
            float4 v = *reinterpret_cast<const float4*>(
                &g_K[(size_t)(bn + r) * CH + h * HD + k0 + c4 * 4]);
            Bs[c4 * 4 + 0][r] = v.x; Bs[c4 * 4 + 1][r] = v.y;
            Bs[c4 * 4 + 2][r] = v.z; Bs[c4 * 4 + 3][r] = v.w;
        }
        __syncthreads();
        #pragma unroll
        for (int k = 0; k < 32; k++) {
            float a[8], b[4];
            #pragma unroll
            for (int i = 0; i < 8; i++) a[i] = As[k][ty * 8 + i];
            #pragma unroll
            for (int j = 0; j < 4; j++) b[j] = Bs[k][tx * 4 + j];
            #pragma unroll
            for (int i = 0; i < 8; i++)
                #pragma unroll
                for (int j = 0; j < 4; j++) acc[i][j] += a[i] * b[j];
        }
        __syncthreads();
    }

    #pragma unroll
    for (int i = 0; i < 8; i++) {
        int m = bm + ty * 8 + i;
        const float* rh = &g_relh[((size_t)h * HW + m) * SH];
        const float* rw = &g_relw[((size_t)h * HW + m) * SH];
        float* orow = &attn[((size_t)h * HW + m) * HW];
        #pragma unroll
        for (int j = 0; j < 4; j++) {
            int n = bn + tx * 4 + j;
            int ky = n / SH, kx = n % SH;
            orow[n] = QSCALE * acc[i][j] + rh[ky] + rw[kx];
        }
    }
}

// ============================================================
// row softmax in place. grid 12*2304 blocks x 256 thr (9 elems/thread)
// ============================================================
__global__ __launch_bounds__(256) void softmax_kernel(float* __restrict__ attn)
{
    float* p = attn + (size_t)blockIdx.x * HW;
    const int t = threadIdx.x;
    float v[9];
    float mx = -1e30f;
    #pragma unroll
    for (int i = 0; i < 9; i++) { v[i] = p[t + i * 256]; mx = fmaxf(mx, v[i]); }

    __shared__ float red[8];
    __shared__ float red2[8];
    #pragma unroll
    for (int o = 16; o; o >>= 1) mx = fmaxf(mx, __shfl_xor_sync(~0u, mx, o));
    if ((t & 31) == 0) red[t >> 5] = mx;
    __syncthreads();
    mx = red[0];
    #pragma unroll
    for (int i = 1; i < 8; i++) mx = fmaxf(mx, red[i]);

    float s = 0.f;
    #pragma unroll
    for (int i = 0; i < 9; i++) { v[i] = __expf(v[i] - mx); s += v[i]; }
    #pragma unroll
    for (int o = 16; o; o >>= 1) s += __shfl_xor_sync(~0u, s, o);
    if ((t & 31) == 0) red2[t >> 5] = s;
    __syncthreads();
    s = 0.f;
    #pragma unroll
    for (int i = 0; i < 8; i++) s += red2[i];
    float inv = 1.0f / s;
    #pragma unroll
    for (int i = 0; i < 9; i++) p[t + i * 256] = v[i] * inv;
}

// ============================================================
// attn . V :  OH[m, h*64+n] = sum_k attn[h,m,k] * V[k, h*64+n]
// per head GEMM-NN: M=2304, N=64, K=2304. grid (18, 1, 12)
// ============================================================
__global__ __launch_bounds__(256) void attnv_kernel(const float* __restrict__ attn)
{
    const int h = blockIdx.z;
    const int bm = blockIdx.x * 128;
    const float* Ah = attn + (size_t)h * HW * HW;

    __shared__ float As[32][129];   // [k][m]
    __shared__ float Bs[32][65];    // [k][n]

    const int tid = threadIdx.x;
    const int tx = tid & 15;
    const int ty = tid >> 4;

    float acc[8][4];
    #pragma unroll
    for (int i = 0; i < 8; i++)
        #pragma unroll
        for (int j = 0; j < 4; j++) acc[i][j] = 0.f;

    for (int k0 = 0; k0 < HW; k0 += 32) {
        // A tile (transposed store)
        #pragma unroll
        for (int i = 0; i < 4; i++) {
            int idx = tid + i * 256;
            int r = idx >> 3, c4 = idx & 7;
            float4 v = *reinterpret_cast<const float4*>(
                &Ah[(size_t)(bm + r) * HW + k0 + c4 * 4]);
            As[c4 * 4 + 0][r] = v.x; As[c4 * 4 + 1][r] = v.y;
            As[c4 * 4 + 2][r] = v.z; As[c4 * 4 + 3][r] = v.w;
        }
        // B tile natural [k][n]: 32 rows x 64 cols = 512 float4 (2 each)
        #pragma unroll
        for (int i = 0; i < 2; i++) {
            int idx = tid + i * 256;
            int r = idx >> 4, c4 = idx & 15;
            float4 v = *reinterpret_cast<const float4*>(
                &g_V[(size_t)(k0 + r) * CH + h * HD + c4 * 4]);
            Bs[r][c4 * 4 + 0] = v.x; Bs[r][c4 * 4 + 1] = v.y;
            Bs[r][c4 * 4 + 2] = v.z; Bs[r][c4 * 4 + 3] = v.w;
        }
        __syncthreads();
        #pragma unroll
        for (int k = 0; k < 32; k++) {
            float a[8], b[4];
            #pragma unroll
            for (int i = 0; i < 8; i++) a[i] = As[k][ty * 8 + i];
            #pragma unroll
            for (int j = 0; j < 4; j++) b[j] = Bs[k][tx * 4 + j];
            #pragma unroll
            for (int i = 0; i < 8; i++)
                #pragma unroll
                for (int j = 0; j < 4; j++) acc[i][j] += a[i] * b[j];
        }
        __syncthreads();
    }

    #pragma unroll
    for (int i = 0; i < 8; i++) {
        int m = bm + ty * 8 + i;
        #pragma unroll
        for (int j = 0; j < 4; j++) {
            int n = tx * 4 + j;
            g_OH[(size_t)m * CH + h * HD + n] = acc[i][j];
        }
    }
}

// ============================================================
// launch
// ============================================================
extern "C" void kernel_launch(void* const* d_in, const int* in_sizes, int n_in,
                              void* d_out, int out_size)
{
    const float* X     = (const float*)d_in[0];   // hidden_states (1,48,48,768)
    const float* wq    = (const float*)d_in[1];
    const float* bq    = (const float*)d_in[2];
    const float* wk    = (const float*)d_in[3];
    const float* bk    = (const float*)d_in[4];
    const float* wv    = (const float*)d_in[5];
    const float* bv    = (const float*)d_in[6];
    const float* wproj = (const float*)d_in[7];
    const float* bproj = (const float*)d_in[8];
    const float* rph   = (const float*)d_in[9];   // (95,64)
    const float* rpw   = (const float*)d_in[10];  // (95,64)

    float* out_ptr  = (float*)d_out;              // (1,48,48,768)
    float* attn_ptr = (float*)d_out + OUT_ELEMS;  // (12,2304,2304)

    dim3 gq(HW / 128, CH / 64);
    gemm_nt_bias<<<gq, 256>>>(X, -1, wq, bq, nullptr, 0);  // -> g_Q
    gemm_nt_bias<<<gq, 256>>>(X, -1, wk, bk, nullptr, 1);  // -> g_K
    gemm_nt_bias<<<gq, 256>>>(X, -1, wv, bv, nullptr, 2);  // -> g_V

    relpos_kernel<<<dim3(HW, NH), 96>>>(rph, rpw);

    scores_kernel<<<dim3(HW / 128, HW / 64, NH), 256>>>(attn_ptr);

    softmax_kernel<<<NH * HW, 256>>>(attn_ptr);

    attnv_kernel<<<dim3(HW / 128, 1, NH), 256>>>(attn_ptr);

    gemm_nt_bias<<<gq, 256>>>(nullptr, 0, wproj, bproj, out_ptr, 3);
}

// round 2
// speedup vs baseline: 1.5341x; 1.5341x over previous
#include <cuda_runtime.h>
#include <cstddef>

#define HW     2304      // 48*48 tokens
#define CH     768       // embed dim
#define NH     12        // heads
#define HD     64        // head dim
#define SH     48        // spatial side
#define QSCALE 0.125f    // 64^-0.5
#define OUT_ELEMS (HW * CH)   // 1769472 — offset of attn region in d_out

// -------- scratch (no allocations allowed) --------
__device__ float g_Q[HW * CH];
__device__ float g_K[HW * CH];
__device__ float g_V[HW * CH];
__device__ float g_OH[HW * CH];
__device__ float g_relh[NH * HW * SH];
__device__ float g_relw[NH * HW * SH];

// ============================================================
// GEMM-NT + bias:  C[m,n] = sum_k A[m,k] * W[n,k] + bias[n]
// M=2304, N=768, K=768.  BM=128, BN=64, BK=32, 256 threads, 8x4/thread.
// asel: -1 -> A = Aext (hidden_states), 0 -> A = g_OH
// csel: 0/1/2 -> g_Q/g_K/g_V, 3 -> Cext
// ============================================================
__global__ __launch_bounds__(256) void gemm_nt_bias(
    const float* __restrict__ Aext, int asel,
    const float* __restrict__ W,
    const float* __restrict__ bias,
    float* __restrict__ Cext, int csel)
{
    const float* A = (asel < 0) ? Aext : g_OH;
    float* Cp = (csel == 0) ? g_Q : (csel == 1) ? g_K : (csel == 2) ? g_V : Cext;

    __shared__ float As[32][129];   // [k][m], pad 129 -> conflict-free transposed stores
    __shared__ float Bs[32][65];    // [k][n]

    const int bm = blockIdx.x * 128;
    const int bn = blockIdx.y * 64;
    const int tid = threadIdx.x;
    const int tx = tid & 15;        // n: 4 each
    const int ty = tid >> 4;        // m: 8 each

    float acc[8][4];
    #pragma unroll
    for (int i = 0; i < 8; i++)
        #pragma unroll
        for (int j = 0; j < 4; j++) acc[i][j] = 0.f;

    for (int k0 = 0; k0 < CH; k0 += 32) {
        // A tile: 128 x 32 = 1024 float4 loads across 256 threads (4 each)
        #pragma unroll
        for (int i = 0; i < 4; i++) {
            int idx = tid + i * 256;
            int r = idx >> 3, c4 = idx & 7;
            float4 v = *reinterpret_cast<const float4*>(
                &A[(size_t)(bm + r) * CH + k0 + c4 * 4]);
            As[c4 * 4 + 0][r] = v.x; As[c4 * 4 + 1][r] = v.y;
            As[c4 * 4 + 2][r] = v.z; As[c4 * 4 + 3][r] = v.w;
        }
        // B tile: 64 x 32 = 512 float4 (2 each)
        #pragma unroll
        for (int i = 0; i < 2; i++) {
            int idx = tid + i * 256;
            int r = idx >> 3, c4 = idx & 7;
            float4 v = *reinterpret_cast<const float4*>(
                &W[(size_t)(bn + r) * CH + k0 + c4 * 4]);
            Bs[c4 * 4 + 0][r] = v.x; Bs[c4 * 4 + 1][r] = v.y;
            Bs[c4 * 4 + 2][r] = v.z; Bs[c4 * 4 + 3][r] = v.w;
        }
        __syncthreads();
        #pragma unroll
        for (int k = 0; k < 32; k++) {
            float a[8], b[4];
            #pragma unroll
            for (int i = 0; i < 8; i++) a[i] = As[k][ty * 8 + i];
            #pragma unroll
            for (int j = 0; j < 4; j++) b[j] = Bs[k][tx * 4 + j];
            #pragma unroll
            for (int i = 0; i < 8; i++)
                #pragma unroll
                for (int j = 0; j < 4; j++) acc[i][j] += a[i] * b[j];
        }
        __syncthreads();
    }

    #pragma unroll
    for (int i = 0; i < 8; i++) {
        int m = bm + ty * 8 + i;
        #pragma unroll
        for (int j = 0; j < 4; j++) {
            int n = bn + tx * 4 + j;
            Cp[(size_t)m * CH + n] = acc[i][j] + bias[n];
        }
    }
}

// ============================================================
// rel-pos bias via batched mini-GEMMs.
// blockIdx = (b, h, z) with z=0 -> relh (b=y), z=1 -> relw (b=x)
// Each block: Qs(48x64) @ Rs(48x64)^T -> 48x48 outputs.
//   relh[h, y*48+x, k] = Q[y*48+x, h*64:] . rph[y-k+47, :]
//   relw[h, y*48+x, k] = Q[y*48+x, h*64:] . rpw[x-k+47, :]
// 256 threads, 3x3 register tile per thread.
// ============================================================
__global__ __launch_bounds__(256) void relpos2(
    const float* __restrict__ rph, const float* __restrict__ rpw)
{
    const int b   = blockIdx.x;    // fixed y (relh) or fixed x (relw)
    const int h   = blockIdx.y;
    const int isW = blockIdx.z;

    __shared__ float Qs[48][68];   // [row][d], stride 68 keeps float4 alignment
    __shared__ float Rs[48][68];   // [k][d]

    const int tid = threadIdx.x;
    const float* rtab = isW ? rpw : rph;

    // Load Q slab (48 rows x 64 d) and R slab (48 k-rows x 64 d): 768 float4 each side
    #pragma unroll
    for (int i = 0; i < 3; i++) {
        int idx = tid + i * 256;
        int r = idx >> 4, c4 = idx & 15;
        int m = isW ? (r * SH + b) : (b * SH + r);
        float4 v = *reinterpret_cast<const float4*>(
            &g_Q[(size_t)m * CH + h * HD + c4 * 4]);
        *reinterpret_cast<float4*>(&Qs[r][c4 * 4]) = v;
        float4 w = *reinterpret_cast<const float4*>(
            &rtab[(size_t)(b - r + SH - 1) * HD + c4 * 4]);
        *reinterpret_cast<float4*>(&Rs[r][c4 * 4]) = w;
    }
    __syncthreads();

    const int tx = tid & 15;       // row group: rows tx*3 .. tx*3+2
    const int ty = tid >> 4;       // k group:   ks   ty*3 .. ty*3+2

    float acc[3][3];
    #pragma unroll
    for (int i = 0; i < 3; i++)
        #pragma unroll
        for (int j = 0; j < 3; j++) acc[i][j] = 0.f;

    #pragma unroll 8
    for (int d = 0; d < HD; d++) {
        float a[3], bb[3];
        #pragma unroll
        for (int i = 0; i < 3; i++) a[i] = Qs[tx * 3 + i][d];
        #pragma unroll
        for (int j = 0; j < 3; j++) bb[j] = Rs[ty * 3 + j][d];
        #pragma unroll
        for (int i = 0; i < 3; i++)
            #pragma unroll
            for (int j = 0; j < 3; j++) acc[i][j] += a[i] * bb[j];
    }

    float* out = isW ? g_relw : g_relh;
    #pragma unroll
    for (int i = 0; i < 3; i++) {
        int r = tx * 3 + i;
        int m = isW ? (r * SH + b) : (b * SH + r);
        float* orow = &out[((size_t)h * HW + m) * SH];
        #pragma unroll
        for (int j = 0; j < 3; j++)
            orow[ty * 3 + j] = acc[i][j];
    }
}

// ============================================================
// scores: attn[h,m,n] = SCALE * (q_h[m] . k_h[n]) + relh[h,m,n/48] + relw[h,m,n%48]
// per head GEMM-NT: M=N=2304, K=64. grid (18, 36, 12)
// ============================================================
__global__ __launch_bounds__(256) void scores_kernel(float* __restrict__ attn)
{
    const int h = blockIdx.z;
    const int bm = blockIdx.x * 128;
    const int bn = blockIdx.y * 64;

    __shared__ float As[32][129];
    __shared__ float Bs[32][65];

    const int tid = threadIdx.x;
    const int tx = tid & 15;
    const int ty = tid >> 4;

    float acc[8][4];
    #pragma unroll
    for (int i = 0; i < 8; i++)
        #pragma unroll
        for (int j = 0; j < 4; j++) acc[i][j] = 0.f;

    for (int k0 = 0; k0 < HD; k0 += 32) {
        #pragma unroll
        for (int i = 0; i < 4; i++) {
            int idx = tid + i * 256;
            int r = idx >> 3, c4 = idx & 7;
            float4 v = *reinterpret_cast<const float4*>(
                &g_Q[(size_t)(bm + r) * CH + h * HD + k0 + c4 * 4]);
            As[c4 * 4 + 0][r] = v.x; As[c4 * 4 + 1][r] = v.y;
            As[c4 * 4 + 2][r] = v.z; As[c4 * 4 + 3][r] = v.w;
        }
        #pragma unroll
        for (int i = 0; i < 2; i++) {
            int idx = tid + i * 256;
            int r = idx >> 3, c4 = idx & 7;
            float4 v = *reinterpret_cast<const float4*>(
                &g_K[(size_t)(bn + r) * CH + h * HD + k0 + c4 * 4]);
            Bs[c4 * 4 + 0][r] = v.x; Bs[c4 * 4 + 1][r] = v.y;
            Bs[c4 * 4 + 2][r] = v.z; Bs[c4 * 4 + 3][r] = v.w;
        }
        __syncthreads();
        #pragma unroll
        for (int k = 0; k < 32; k++) {
            float a[8], b[4];
            #pragma unroll
            for (int i = 0; i < 8; i++) a[i] = As[k][ty * 8 + i];
            #pragma unroll
            for (int j = 0; j < 4; j++) b[j] = Bs[k][tx * 4 + j];
            #pragma unroll
            for (int i = 0; i < 8; i++)
                #pragma unroll
                for (int j = 0; j < 4; j++) acc[i][j] += a[i] * b[j];
        }
        __syncthreads();
    }

    #pragma unroll
    for (int i = 0; i < 8; i++) {
        int m = bm + ty * 8 + i;
        const float* rh = &g_relh[((size_t)h * HW + m) * SH];
        const float* rw = &g_relw[((size_t)h * HW + m) * SH];
        float* orow = &attn[((size_t)h * HW + m) * HW];
        #pragma unroll
        for (int j = 0; j < 4; j++) {
            int n = bn + tx * 4 + j;
            int ky = n / SH, kx = n % SH;
            orow[n] = QSCALE * acc[i][j] + rh[ky] + rw[kx];
        }
    }
}

// ============================================================
// row softmax in place. grid 12*2304 blocks x 256 thr (9 elems/thread)
// ============================================================
__global__ __launch_bounds__(256) void softmax_kernel(float* __restrict__ attn)
{
    float* p = attn + (size_t)blockIdx.x * HW;
    const int t = threadIdx.x;
    float v[9];
    float mx = -1e30f;
    #pragma unroll
    for (int i = 0; i < 9; i++) { v[i] = p[t + i * 256]; mx = fmaxf(mx, v[i]); }

    __shared__ float red[8];
    __shared__ float red2[8];
    #pragma unroll
    for (int o = 16; o; o >>= 1) mx = fmaxf(mx, __shfl_xor_sync(~0u, mx, o));
    if ((t & 31) == 0) red[t >> 5] = mx;
    __syncthreads();
    mx = red[0];
    #pragma unroll
    for (int i = 1; i < 8; i++) mx = fmaxf(mx, red[i]);

    float s = 0.f;
    #pragma unroll
    for (int i = 0; i < 9; i++) { v[i] = __expf(v[i] - mx); s += v[i]; }
    #pragma unroll
    for (int o = 16; o; o >>= 1) s += __shfl_xor_sync(~0u, s, o);
    if ((t & 31) == 0) red2[t >> 5] = s;
    __syncthreads();
    s = 0.f;
    #pragma unroll
    for (int i = 0; i < 8; i++) s += red2[i];
    float inv = 1.0f / s;
    #pragma unroll
    for (int i = 0; i < 9; i++) p[t + i * 256] = v[i] * inv;
}

// ============================================================
// attn . V :  OH[m, h*64+n] = sum_k attn[h,m,k] * V[k, h*64+n]
// per head GEMM-NN: M=2304, N=64, K=2304. grid (18, 1, 12)
// ============================================================
__global__ __launch_bounds__(256) void attnv_kernel(const float* __restrict__ attn)
{
    const int h = blockIdx.z;
    const int bm = blockIdx.x * 128;
    const float* Ah = attn + (size_t)h * HW * HW;

    __shared__ float As[32][129];   // [k][m]
    __shared__ float Bs[32][65];    // [k][n]

    const int tid = threadIdx.x;
    const int tx = tid & 15;
    const int ty = tid >> 4;

    float acc[8][4];
    #pragma unroll
    for (int i = 0; i < 8; i++)
        #pragma unroll
        for (int j = 0; j < 4; j++) acc[i][j] = 0.f;

    for (int k0 = 0; k0 < HW; k0 += 32) {
        // A tile (transposed store)
        #pragma unroll
        for (int i = 0; i < 4; i++) {
            int idx = tid + i * 256;
            int r = idx >> 3, c4 = idx & 7;
            float4 v = *reinterpret_cast<const float4*>(
                &Ah[(size_t)(bm + r) * HW + k0 + c4 * 4]);
            As[c4 * 4 + 0][r] = v.x; As[c4 * 4 + 1][r] = v.y;
            As[c4 * 4 + 2][r] = v.z; As[c4 * 4 + 3][r] = v.w;
        }
        // B tile natural [k][n]: 32 rows x 64 cols = 512 float4 (2 each)
        #pragma unroll
        for (int i = 0; i < 2; i++) {
            int idx = tid + i * 256;
            int r = idx >> 4, c4 = idx & 15;
            float4 v = *reinterpret_cast<const float4*>(
                &g_V[(size_t)(k0 + r) * CH + h * HD + c4 * 4]);
            Bs[r][c4 * 4 + 0] = v.x; Bs[r][c4 * 4 + 1] = v.y;
            Bs[r][c4 * 4 + 2] = v.z; Bs[r][c4 * 4 + 3] = v.w;
        }
        __syncthreads();
        #pragma unroll
        for (int k = 0; k < 32; k++) {
            float a[8], b[4];
            #pragma unroll
            for (int i = 0; i < 8; i++) a[i] = As[k][ty * 8 + i];
            #pragma unroll
            for (int j = 0; j < 4; j++) b[j] = Bs[k][tx * 4 + j];
            #pragma unroll
            for (int i = 0; i < 8; i++)
                #pragma unroll
                for (int j = 0; j < 4; j++) acc[i][j] += a[i] * b[j];
        }
        __syncthreads();
    }

    #pragma unroll
    for (int i = 0; i < 8; i++) {
        int m = bm + ty * 8 + i;
        #pragma unroll
        for (int j = 0; j < 4; j++) {
            int n = tx * 4 + j;
            g_OH[(size_t)m * CH + h * HD + n] = acc[i][j];
        }
    }
}

// ============================================================
// launch
// ============================================================
extern "C" void kernel_launch(void* const* d_in, const int* in_sizes, int n_in,
                              void* d_out, int out_size)
{
    const float* X     = (const float*)d_in[0];   // hidden_states (1,48,48,768)
    const float* wq    = (const float*)d_in[1];
    const float* bq    = (const float*)d_in[2];
    const float* wk    = (const float*)d_in[3];
    const float* bk    = (const float*)d_in[4];
    const float* wv    = (const float*)d_in[5];
    const float* bv    = (const float*)d_in[6];
    const float* wproj = (const float*)d_in[7];
    const float* bproj = (const float*)d_in[8];
    const float* rph   = (const float*)d_in[9];   // (95,64)
    const float* rpw   = (const float*)d_in[10];  // (95,64)

    float* out_ptr  = (float*)d_out;              // (1,48,48,768)
    float* attn_ptr = (float*)d_out + OUT_ELEMS;  // (12,2304,2304)

    dim3 gq(HW / 128, CH / 64);
    gemm_nt_bias<<<gq, 256>>>(X, -1, wq, bq, nullptr, 0);  // -> g_Q
    gemm_nt_bias<<<gq, 256>>>(X, -1, wk, bk, nullptr, 1);  // -> g_K
    gemm_nt_bias<<<gq, 256>>>(X, -1, wv, bv, nullptr, 2);  // -> g_V

    relpos2<<<dim3(SH, NH, 2), 256>>>(rph, rpw);

    scores_kernel<<<dim3(HW / 128, HW / 64, NH), 256>>>(attn_ptr);

    softmax_kernel<<<NH * HW, 256>>>(attn_ptr);

    attnv_kernel<<<dim3(HW / 128, 1, NH), 256>>>(attn_ptr);

    gemm_nt_bias<<<gq, 256>>>(nullptr, 0, wproj, bproj, out_ptr, 3);
}

// round 4
// speedup vs baseline: 2.7427x; 1.7878x over previous
#include <cuda_runtime.h>
#include <cuda_bf16.h>
#include <cstddef>
#include <cstdint>

#define HW     2304
#define CH     768
#define NH     12
#define HD     64
#define SH     48
#define QSCALE 0.125f
#define OUT_ELEMS (HW * CH)

// smem layout (relative to 1024-aligned base), bf16 tiles
#define A_HI  0          // 128 x 64 bf16 = 16384 B
#define A_LO  16384
#define B_HI  32768      // 64 x 64 bf16 = 8192 B
#define B_LO  40960
#define SMEM_BYTES (49152 + 1024)

// -------- scratch --------
__device__ float g_Q[HW * CH];
__device__ float g_K[HW * CH];
__device__ float g_Vt[CH * HW];     // transposed V: [n][m]
__device__ float g_OH[HW * CH];
__device__ float g_relh[NH * HW * SH];
__device__ float g_relw[NH * HW * SH];

// ---------------- helpers ----------------
__device__ __forceinline__ uint32_t smem_u32(const void* p) {
    uint32_t a;
    asm("{ .reg .u64 t; cvta.to.shared.u64 t, %1; cvt.u32.u64 %0, t; }" : "=r"(a) : "l"(p));
    return a;
}

__device__ __forceinline__ void ldsm4(uint32_t* r, uint32_t addr) {
    asm volatile("ldmatrix.sync.aligned.m8n8.x4.shared.b16 {%0,%1,%2,%3}, [%4];"
        : "=r"(r[0]), "=r"(r[1]), "=r"(r[2]), "=r"(r[3]) : "r"(addr));
}

__device__ __forceinline__ void mma16816(float* d, const uint32_t* a, const uint32_t* b) {
    asm volatile("mma.sync.aligned.m16n8k16.row.col.f32.bf16.bf16.f32 "
        "{%0,%1,%2,%3}, {%4,%5,%6,%7}, {%8,%9}, {%0,%1,%2,%3};"
        : "+f"(d[0]), "+f"(d[1]), "+f"(d[2]), "+f"(d[3])
        : "r"(a[0]), "r"(a[1]), "r"(a[2]), "r"(a[3]), "r"(b[0]), "r"(b[1]));
}

// split fp32x4 -> packed bf16 hi pairs + lo pairs
__device__ __forceinline__ void split4(float4 v, uint32_t& h0, uint32_t& h1,
                                       uint32_t& l0, uint32_t& l1) {
    __nv_bfloat16 hx = __float2bfloat16(v.x), hy = __float2bfloat16(v.y);
    __nv_bfloat16 hz = __float2bfloat16(v.z), hw = __float2bfloat16(v.w);
    __nv_bfloat16 lx = __float2bfloat16(v.x - __bfloat162float(hx));
    __nv_bfloat16 ly = __float2bfloat16(v.y - __bfloat162float(hy));
    __nv_bfloat16 lz = __float2bfloat16(v.z - __bfloat162float(hz));
    __nv_bfloat16 lw = __float2bfloat16(v.w - __bfloat162float(hw));
    h0 = ((uint32_t)__bfloat16_as_ushort(hy) << 16) | __bfloat16_as_ushort(hx);
    h1 = ((uint32_t)__bfloat16_as_ushort(hw) << 16) | __bfloat16_as_ushort(hz);
    l0 = ((uint32_t)__bfloat16_as_ushort(ly) << 16) | __bfloat16_as_ushort(lx);
    l1 = ((uint32_t)__bfloat16_as_ushort(lw) << 16) | __bfloat16_as_ushort(lz);
}

__device__ __forceinline__ uint32_t sw128(uint32_t off) {
    return off ^ ((off >> 3) & 0x70);
}
__device__ __forceinline__ void st8_sw(char* base, uint32_t byteoff, uint32_t a, uint32_t b) {
    *reinterpret_cast<uint2*>(base + sw128(byteoff)) = make_uint2(a, b);
}

// ============================================================
// Generic mma.sync bf16x3 NT GEMM: C[m,n] = sum_k A[m,k]*B[n,k]
// BM=128, BN=64, BK=64, 256 threads, 8 warps (4 m x 2 n), 32x32/warp.
// asel: 0=Aext 1=g_Q 2=g_OH ; bsel: 0=Bext 1=g_K 2=g_Vt
// mode: 0 = C+bias ; 1 = g_Vt[n*HW+m]=acc+bias[n] ; 2 = scores ; 3 = plain
// ============================================================
__global__ __launch_bounds__(256) void tc_gemm(
    const float* __restrict__ Aext, int asel, int lda, unsigned long long aoffz,
    const float* __restrict__ Bext, int bsel, int ldb, unsigned long long boffz,
    float* __restrict__ Cext, int csel, int ldc, unsigned long long coffz,
    const float* __restrict__ bias, int kk, int mode)
{
    extern __shared__ char dsm[];
    uint32_t raw = smem_u32(dsm);
    uint32_t sb = (raw + 1023) & ~1023u;
    char* sp = dsm + (sb - raw);

    const int tid = threadIdx.x;
    const int wid = tid >> 5;
    const uint32_t lane = tid & 31;
    const int bm = blockIdx.x * 128;
    const int bn = blockIdx.y * 64;
    const int h  = blockIdx.z;

    const float* A = (asel == 1) ? g_Q : (asel == 2) ? g_OH : Aext;
    const float* B = (bsel == 1) ? g_K : (bsel == 2) ? g_Vt : Bext;
    float* C = (csel == 1) ? g_Q : (csel == 2) ? g_K : (csel == 3) ? g_OH : Cext;
    A += (size_t)h * aoffz;
    B += (size_t)h * boffz;
    C += (size_t)h * coffz;

    const int wm = wid & 3;        // m warp tile (32 rows)
    const int wn = wid >> 2;       // n warp tile (32 cols)

    // ldmatrix per-lane row/col offsets
    const int a_r = lane & 15;
    const int a_c = (lane >> 4) * 8;
    const int b_r = (lane & 7) + ((lane >> 4) & 1) * 8;
    const int b_c = ((lane >> 3) & 1) * 8;

    float acc[2][4][4];
    #pragma unroll
    for (int o = 0; o < 2; o++)
        #pragma unroll
        for (int j = 0; j < 4; j++)
            #pragma unroll
            for (int e = 0; e < 4; e++) acc[o][j][e] = 0.f;

    for (int c = 0; c < kk; c++) {
        const int k0 = c * 64;
        // A tile: 128 x 64 fp32 -> bf16 hi/lo swizzled
        #pragma unroll
        for (int i = 0; i < 8; i++) {
            int idx = tid + i * 256;
            int r = idx >> 4, c4 = idx & 15;
            float4 v = *reinterpret_cast<const float4*>(
                &A[(size_t)(bm + r) * lda + k0 + c4 * 4]);
            uint32_t h0, h1, l0, l1;
            split4(v, h0, h1, l0, l1);
            uint32_t bo = r * 128 + c4 * 8;
            st8_sw(sp + A_HI, bo, h0, h1);
            st8_sw(sp + A_LO, bo, l0, l1);
        }
        // B tile: 64 x 64
        #pragma unroll
        for (int i = 0; i < 4; i++) {
            int idx = tid + i * 256;
            int r = idx >> 4, c4 = idx & 15;
            float4 v = *reinterpret_cast<const float4*>(
                &B[(size_t)(bn + r) * ldb + k0 + c4 * 4]);
            uint32_t h0, h1, l0, l1;
            split4(v, h0, h1, l0, l1);
            uint32_t bo = r * 128 + c4 * 8;
            st8_sw(sp + B_HI, bo, h0, h1);
            st8_sw(sp + B_LO, bo, l0, l1);
        }
        __syncthreads();

        #pragma unroll
        for (int ks = 0; ks < 4; ks++) {
            uint32_t ahi[2][4], alo[2][4], bhi[2][4], blo[2][4];
            #pragma unroll
            for (int o = 0; o < 2; o++) {
                uint32_t off = (uint32_t)(wm * 32 + o * 16 + a_r) * 128
                             + (uint32_t)(ks * 16 + a_c) * 2;
                uint32_t s = sw128(off);
                ldsm4(ahi[o], sb + A_HI + s);
                ldsm4(alo[o], sb + A_LO + s);
            }
            #pragma unroll
            for (int g = 0; g < 2; g++) {
                uint32_t off = (uint32_t)(wn * 32 + g * 16 + b_r) * 128
                             + (uint32_t)(ks * 16 + b_c) * 2;
                uint32_t s = sw128(off);
                ldsm4(bhi[g], sb + B_HI + s);
                ldsm4(blo[g], sb + B_LO + s);
            }
            #pragma unroll
            for (int o = 0; o < 2; o++)
                #pragma unroll
                for (int j = 0; j < 4; j++) {
                    const uint32_t* bh = &bhi[j >> 1][(j & 1) * 2];
                    const uint32_t* bl = &blo[j >> 1][(j & 1) * 2];
                    mma16816(acc[o][j], ahi[o], bh);
                    mma16816(acc[o][j], ahi[o], bl);
                    mma16816(acc[o][j], alo[o], bh);
                }
        }
        __syncthreads();
    }

    // ---------------- epilogue: stage D in smem, coalesced write ----------------
    float* Ds = reinterpret_cast<float*>(sp);   // 128 x 68 floats
    #pragma unroll
    for (int o = 0; o < 2; o++)
        #pragma unroll
        for (int j = 0; j < 4; j++) {
            int ml = wm * 32 + o * 16 + (int)(lane >> 2);
            int nl = wn * 32 + j * 8 + (int)(lane & 3) * 2;
            *reinterpret_cast<float2*>(&Ds[ml * 68 + nl]) =
                make_float2(acc[o][j][0], acc[o][j][1]);
            *reinterpret_cast<float2*>(&Ds[(ml + 8) * 68 + nl]) =
                make_float2(acc[o][j][2], acc[o][j][3]);
        }
    __syncthreads();

    if (mode == 1) {
        // transposed write: g_Vt[n][m] = acc + bias[n]
        #pragma unroll
        for (int i = 0; i < 32; i++) {
            int idx = tid + i * 256;          // 8192 elements
            int rr = idx & 127, nc = idx >> 7;
            int n = bn + nc;
            g_Vt[(size_t)n * HW + bm + rr] = Ds[rr * 68 + nc] + bias[n];
        }
    } else {
        #pragma unroll
        for (int i = 0; i < 8; i++) {
            int idx = tid + i * 256;
            int rr = idx >> 4, c4 = idx & 15;
            int m = bm + rr;
            float* pv = &Ds[rr * 68 + c4 * 4];
            float v0 = pv[0], v1 = pv[1], v2 = pv[2], v3 = pv[3];
            float4 o;
            if (mode == 0) {
                int n = bn + c4 * 4;
                o.x = v0 + bias[n]; o.y = v1 + bias[n + 1];
                o.z = v2 + bias[n + 2]; o.w = v3 + bias[n + 3];
            } else if (mode == 2) {
                size_t rb = ((size_t)h * HW + m) * SH;
                int n = bn + c4 * 4;
                o.x = QSCALE * v0 + g_relh[rb + (n    ) / SH] + g_relw[rb + (n    ) % SH];
                o.y = QSCALE * v1 + g_relh[rb + (n + 1) / SH] + g_relw[rb + (n + 1) % SH];
                o.z = QSCALE * v2 + g_relh[rb + (n + 2) / SH] + g_relw[rb + (n + 2) % SH];
                o.w = QSCALE * v3 + g_relh[rb + (n + 3) / SH] + g_relw[rb + (n + 3) % SH];
            } else {
                o.x = v0; o.y = v1; o.z = v2; o.w = v3;
            }
            *reinterpret_cast<float4*>(&C[(size_t)m * ldc + bn + c4 * 4]) = o;
        }
    }
}

// ============================================================
// rel-pos bias via batched mini-GEMMs (unchanged)
// ============================================================
__global__ __launch_bounds__(256) void relpos2(
    const float* __restrict__ rph, const float* __restrict__ rpw)
{
    const int b   = blockIdx.x;
    const int h   = blockIdx.y;
    const int isW = blockIdx.z;

    __shared__ float Qs[48][68];
    __shared__ float Rs[48][68];

    const int tid = threadIdx.x;
    const float* rtab = isW ? rpw : rph;

    #pragma unroll
    for (int i = 0; i < 3; i++) {
        int idx = tid + i * 256;
        int r = idx >> 4, c4 = idx & 15;
        int m = isW ? (r * SH + b) : (b * SH + r);
        float4 v = *reinterpret_cast<const float4*>(
            &g_Q[(size_t)m * CH + h * HD + c4 * 4]);
        *reinterpret_cast<float4*>(&Qs[r][c4 * 4]) = v;
        float4 w = *reinterpret_cast<const float4*>(
            &rtab[(size_t)(b - r + SH - 1) * HD + c4 * 4]);
        *reinterpret_cast<float4*>(&Rs[r][c4 * 4]) = w;
    }
    __syncthreads();

    const int tx = tid & 15;
    const int ty = tid >> 4;

    float acc[3][3];
    #pragma unroll
    for (int i = 0; i < 3; i++)
        #pragma unroll
        for (int j = 0; j < 3; j++) acc[i][j] = 0.f;

    #pragma unroll 8
    for (int d = 0; d < HD; d++) {
        float a[3], bb[3];
        #pragma unroll
        for (int i = 0; i < 3; i++) a[i] = Qs[tx * 3 + i][d];
        #pragma unroll
        for (int j = 0; j < 3; j++) bb[j] = Rs[ty * 3 + j][d];
        #pragma unroll
        for (int i = 0; i < 3; i++)
            #pragma unroll
            for (int j = 0; j < 3; j++) acc[i][j] += a[i] * bb[j];
    }

    float* out = isW ? g_relw : g_relh;
    #pragma unroll
    for (int i = 0; i < 3; i++) {
        int rr = tx * 3 + i;
        int m = isW ? (rr * SH + b) : (b * SH + rr);
        float* orow = &out[((size_t)h * HW + m) * SH];
        #pragma unroll
        for (int j = 0; j < 3; j++)
            orow[ty * 3 + j] = acc[i][j];
    }
}

// ============================================================
// row softmax in place (unchanged)
// ============================================================
__global__ __launch_bounds__(256) void softmax_kernel(float* __restrict__ attn)
{
    float* p = attn + (size_t)blockIdx.x * HW;
    const int t = threadIdx.x;
    float v[9];
    float mx = -1e30f;
    #pragma unroll
    for (int i = 0; i < 9; i++) { v[i] = p[t + i * 256]; mx = fmaxf(mx, v[i]); }

    __shared__ float red[8];
    __shared__ float red2[8];
    #pragma unroll
    for (int o = 16; o; o >>= 1) mx = fmaxf(mx, __shfl_xor_sync(~0u, mx, o));
    if ((t & 31) == 0) red[t >> 5] = mx;
    __syncthreads();
    mx = red[0];
    #pragma unroll
    for (int i = 1; i < 8; i++) mx = fmaxf(mx, red[i]);

    float s = 0.f;
    #pragma unroll
    for (int i = 0; i < 9; i++) { v[i] = __expf(v[i] - mx); s += v[i]; }
    #pragma unroll
    for (int o = 16; o; o >>= 1) s += __shfl_xor_sync(~0u, s, o);
    if ((t & 31) == 0) red2[t >> 5] = s;
    __syncthreads();
    s = 0.f;
    #pragma unroll
    for (int i = 0; i < 8; i++) s += red2[i];
    float inv = 1.0f / s;
    #pragma unroll
    for (int i = 0; i < 9; i++) p[t + i * 256] = v[i] * inv;
}

// ============================================================
// launch
// ============================================================
extern "C" void kernel_launch(void* const* d_in, const int* in_sizes, int n_in,
                              void* d_out, int out_size)
{
    const float* X     = (const float*)d_in[0];
    const float* wq    = (const float*)d_in[1];
    const float* bq    = (const float*)d_in[2];
    const float* wk    = (const float*)d_in[3];
    const float* bk    = (const float*)d_in[4];
    const float* wv    = (const float*)d_in[5];
    const float* bv    = (const float*)d_in[6];
    const float* wproj = (const float*)d_in[7];
    const float* bproj = (const float*)d_in[8];
    const float* rph   = (const float*)d_in[9];
    const float* rpw   = (const float*)d_in[10];

    float* out_ptr  = (float*)d_out;
    float* attn_ptr = (float*)d_out + OUT_ELEMS;

    cudaFuncSetAttribute(tc_gemm, cudaFuncAttributeMaxDynamicSharedMemorySize, SMEM_BYTES);

    // Q, K, V projections (V -> transposed g_Vt)
    tc_gemm<<<dim3(18, 12, 1), 256, SMEM_BYTES>>>(
        X, 0, CH, 0, wq, 0, CH, 0, nullptr, 1, CH, 0, bq, 12, 0);
    tc_gemm<<<dim3(18, 12, 1), 256, SMEM_BYTES>>>(
        X, 0, CH, 0, wk, 0, CH, 0, nullptr, 2, CH, 0, bk, 12, 0);
    tc_gemm<<<dim3(18, 12, 1), 256, SMEM_BYTES>>>(
        X, 0, CH, 0, wv, 0, CH, 0, nullptr, 0, CH, 0, bv, 12, 1);

    relpos2<<<dim3(SH, NH, 2), 256>>>(rph, rpw);

    // scores: per head, A=g_Q(+h*64), B=g_K(+h*64), C=attn(+h*HW*HW)
    tc_gemm<<<dim3(18, 36, NH), 256, SMEM_BYTES>>>(
        nullptr, 1, CH, 64ULL, nullptr, 1, CH, 64ULL,
        attn_ptr, 0, HW, (unsigned long long)HW * HW, nullptr, 1, 2);

    softmax_kernel<<<NH * HW, 256>>>(attn_ptr);

    // attn . V : A=attn(+h*HW*HW), B=g_Vt(+h*64*HW), C=g_OH(+h*64)
    tc_gemm<<<dim3(18, 1, NH), 256, SMEM_BYTES>>>(
        attn_ptr, 0, HW, (unsigned long long)HW * HW,
        nullptr, 2, HW, 64ULL * HW,
        nullptr, 3, CH, 64ULL, nullptr, 36, 3);

    // output projection
    tc_gemm<<<dim3(18, 12, 1), 256, SMEM_BYTES>>>(
        nullptr, 2, CH, 0, wproj, 0, CH, 0, out_ptr, 0, CH, 0, bproj, 12, 0);
}